// round 12
// baseline (speedup 1.0000x reference)
#include <cuda_runtime.h>
#include <cuda_fp16.h>
#include <cstdint>

// ---------------- problem constants ----------------
#define NN 100000
#define EE 1600000
#define NG 512
#define D  100      // hidden dim
#define K1 128      // input feature dim
#define SCAN_B ((NN + 255) / 256)   // 391 scan blocks

// ---------------- device scratch (static globals: allocation-free) ----------------
__device__ int    g_deg[NN];
__device__ int    g_cursor[NN];
__device__ int    g_off[NN];
__device__ int    g_part[512];
__device__ int    g_csr[EE];
__device__ float  g_dinv_s[NN];
__device__ float  g_dinv_n[NN];
__device__ __half g_t0[(size_t)NN * D];   // gathered operands stored fp16
__device__ float  g_h1[(size_t)NN * D];
__device__ __half g_t1[(size_t)NN * D];
__device__ float  g_h2[(size_t)NN * D];
__device__ __half g_u[(size_t)NN * D];    // ARMA propagated input (gathered)
__device__ float  g_r[(size_t)NN * D];    // ARMA root part (node-local)
__device__ float  g_sum[D];
__device__ float  g_sumsq[D];
__device__ float  g_Wur[D * 200];         // BN-folded [Wa_init | Wa_root]
__device__ float  g_bur[200];
__device__ float  g_pool[NG * D];
__device__ float  g_m1[NG * 200];
__device__ float  g_m2[NG * 300];
__device__ float  g_m3[NG * 200];

// ---------------- packed f32x2 fma (exact fp32, 2 MACs/instr) ----------------
__device__ __forceinline__ void fma2(unsigned long long& d, unsigned long long a,
                                     unsigned long long b) {
    asm("fma.rn.f32x2 %0, %1, %2, %0;" : "+l"(d) : "l"(a), "l"(b));
}
__device__ __forceinline__ void unpack2(unsigned long long v, float& lo, float& hi) {
    asm("mov.b64 {%0, %1}, %2;" : "=f"(lo), "=f"(hi) : "l"(v));
}

// ---------------- init ----------------
__global__ void zero_kernel() {
    int i = blockIdx.x * blockDim.x + threadIdx.x;
    int stride = gridDim.x * blockDim.x;
    for (int k = i; k < NN; k += stride) { g_deg[k] = 0; g_cursor[k] = 0; }
    for (int k = i; k < NG * D; k += stride) g_pool[k] = 0.f;
    if (i < D) { g_sum[i] = 0.f; g_sumsq[i] = 0.f; }
}

// ---------------- graph-build kernels ----------------
__global__ void deg_kernel(const int* __restrict__ dst) {
    int e = blockIdx.x * blockDim.x + threadIdx.x;
    if (e < EE) atomicAdd(&g_deg[dst[e]], 1);
}

__global__ void scan1_kernel() {
    __shared__ int sh[256];
    int tid = threadIdx.x;
    int i = blockIdx.x * 256 + tid;
    int v = (i < NN) ? g_deg[i] : 0;
    sh[tid] = v;
    __syncthreads();
    for (int ofs = 1; ofs < 256; ofs <<= 1) {
        int t = (tid >= ofs) ? sh[tid - ofs] : 0;
        __syncthreads();
        sh[tid] += t;
        __syncthreads();
    }
    if (i < NN) {
        g_off[i] = sh[tid] - v;
        g_dinv_s[i] = rsqrtf((float)(v + 1));
        g_dinv_n[i] = (v > 0) ? rsqrtf((float)v) : 0.f;
    }
    if (tid == 255) g_part[blockIdx.x] = sh[255];
}

__global__ void scan2_kernel() {
    __shared__ int sh[512];
    int tid = threadIdx.x;
    int v = (tid < SCAN_B) ? g_part[tid] : 0;
    sh[tid] = v;
    __syncthreads();
    for (int ofs = 1; ofs < 512; ofs <<= 1) {
        int t = (tid >= ofs) ? sh[tid - ofs] : 0;
        __syncthreads();
        sh[tid] += t;
        __syncthreads();
    }
    g_part[tid] = sh[tid] - v;
}

__global__ void csrfill_kernel(const int* __restrict__ src, const int* __restrict__ dst) {
    int e = blockIdx.x * blockDim.x + threadIdx.x;
    if (e < EE) {
        int d = dst[e];
        int pos = g_off[d] + g_part[d >> 8] + atomicAdd(&g_cursor[d], 1);
        g_csr[pos] = src[e];
    }
}

// ---------------- fp16 pack/unpack helpers ----------------
__device__ __forceinline__ void store_half4(__half* p, float a, float b, float c, float d) {
    __half2 h0 = __floats2half2_rn(a, b);
    __half2 h1 = __floats2half2_rn(c, d);
    uint2 pk;
    pk.x = *(unsigned*)&h0;
    pk.y = *(unsigned*)&h1;
    *(uint2*)p = pk;
}
__device__ __forceinline__ float4 load_half4(const __half* p) {
    uint2 pk = *(const uint2*)p;
    float2 f0 = __half22float2(*(__half2*)&pk.x);
    float2 f1 = __half22float2(*(__half2*)&pk.y);
    return make_float4(f0.x, f0.y, f1.x, f1.y);
}

// ---------------- f32x2 node GEMM: C[n x 100] = A[n x K] @ W[K x 100] (+bias) ----------------
// Block 80 rows x 100 cols, 256 threads (250 active: 25 col-groups x 10 row-groups).
// X stored DUPLICATED (x,x) in smem -> LDS.128 yields two b64 (x,x) operands directly.
// W column pairs are adjacent -> one LDS.128 = (w0,w1),(w2,w3) b64 operands. No packing movs.
// Per thread-k: 5 LDS.128 + 16 FFMA2.
template <int K, int KC, bool HALF_OUT>
__global__ void __launch_bounds__(256, 4)
gemm_rf2(const float* __restrict__ A, const float* __restrict__ W,
         const float* __restrict__ bias, void* __restrict__ Cv) {
    constexpr int ROWS = 80;               // 1250 blocks * 80 = NN exactly
    constexpr int XP2 = 2 * ROWS + 4;      // 164 floats (656B, 16B-aligned)
    __shared__ __align__(16) float Xs[KC * XP2];
    __shared__ __align__(16) float Ws[KC * D];
    int tid = threadIdx.x;
    int rowbase = blockIdx.x * ROWS;
    bool active = tid < 250;
    int cx = tid % 25;                     // cols 4*cx .. 4*cx+3
    int ry = active ? (tid / 25) : 0;      // rows 8*ry .. 8*ry+7

    unsigned long long acc[8][2];
#pragma unroll
    for (int i = 0; i < 8; i++) { acc[i][0] = 0ull; acc[i][1] = 0ull; }

    for (int k0 = 0; k0 < K; k0 += KC) {
        for (int idx = tid; idx < KC * (D / 4); idx += 256)
            ((float4*)Ws)[idx] = ((const float4*)(W + (size_t)k0 * D))[idx];
        for (int idx = tid; idx < ROWS * KC; idx += 256) {
            int r = idx / KC, k = idx % KC;
            float v = A[(size_t)(rowbase + r) * K + k0 + k];
            *(float2*)&Xs[k * XP2 + 2 * r] = make_float2(v, v);
        }
        __syncthreads();

#pragma unroll 2
        for (int k = 0; k < KC; k++) {
            const ulonglong2 wp = *(const ulonglong2*)&Ws[k * D + cx * 4];
            const ulonglong2* xrow = (const ulonglong2*)&Xs[k * XP2 + ry * 16];
            ulonglong2 x0 = xrow[0], x1 = xrow[1], x2 = xrow[2], x3 = xrow[3];
            unsigned long long xd[8] = {x0.x, x0.y, x1.x, x1.y, x2.x, x2.y, x3.x, x3.y};
#pragma unroll
            for (int i = 0; i < 8; i++) {
                fma2(acc[i][0], xd[i], wp.x);
                fma2(acc[i][1], xd[i], wp.y);
            }
        }
        __syncthreads();
    }

    if (active) {
        float4 bb = make_float4(0.f, 0.f, 0.f, 0.f);
        if (bias) bb = *(const float4*)&bias[cx * 4];
#pragma unroll
        for (int i = 0; i < 8; i++) {
            int gr = rowbase + ry * 8 + i;
            float c0, c1, c2, c3;
            unpack2(acc[i][0], c0, c1);
            unpack2(acc[i][1], c2, c3);
            c0 += bb.x; c1 += bb.y; c2 += bb.z; c3 += bb.w;
            if (HALF_OUT) store_half4((__half*)Cv + (size_t)gr * D + cx * 4, c0, c1, c2, c3);
            else *(float4*)((float*)Cv + (size_t)gr * D + cx * 4) = make_float4(c0, c1, c2, c3);
        }
    }
}

// ---------------- merged ARMA GEMM (f32x2): [U | R] = A[n x 100] @ Wur[100 x 200] + bur -------
template <int K, int KC>
__global__ void __launch_bounds__(256, 4)
gemm_ur2(const float* __restrict__ A, const float* __restrict__ W,
         const float* __restrict__ bias, __half* __restrict__ U, float* __restrict__ R) {
    constexpr int NC = 200;
    constexpr int ROWS = 40;               // 2500 blocks * 40 = NN exactly
    constexpr int XP2 = 2 * ROWS + 4;      // 84 floats (336B, 16B-aligned)
    __shared__ __align__(16) float Xs[KC * XP2];
    __shared__ __align__(16) float Ws[KC * NC];
    int tid = threadIdx.x;
    int rowbase = blockIdx.x * ROWS;
    bool active = tid < 250;
    int cx = tid % 50;
    int ry = active ? (tid / 50) : 0;

    unsigned long long acc[8][2];
#pragma unroll
    for (int i = 0; i < 8; i++) { acc[i][0] = 0ull; acc[i][1] = 0ull; }

    for (int k0 = 0; k0 < K; k0 += KC) {
        for (int idx = tid; idx < KC * (NC / 4); idx += 256)
            ((float4*)Ws)[idx] = ((const float4*)(W + (size_t)k0 * NC))[idx];
        for (int idx = tid; idx < ROWS * KC; idx += 256) {
            int r = idx / KC, k = idx % KC;
            float v = A[(size_t)(rowbase + r) * K + k0 + k];
            *(float2*)&Xs[k * XP2 + 2 * r] = make_float2(v, v);
        }
        __syncthreads();

#pragma unroll 2
        for (int k = 0; k < KC; k++) {
            const ulonglong2 wp = *(const ulonglong2*)&Ws[k * NC + cx * 4];
            const ulonglong2* xrow = (const ulonglong2*)&Xs[k * XP2 + ry * 16];
            ulonglong2 x0 = xrow[0], x1 = xrow[1], x2 = xrow[2], x3 = xrow[3];
            unsigned long long xd[8] = {x0.x, x0.y, x1.x, x1.y, x2.x, x2.y, x3.x, x3.y};
#pragma unroll
            for (int i = 0; i < 8; i++) {
                fma2(acc[i][0], xd[i], wp.x);
                fma2(acc[i][1], xd[i], wp.y);
            }
        }
        __syncthreads();
    }

    if (active) {
        int c = cx * 4;
        float4 bb = *(const float4*)&bias[c];
        bool isU = c < D;
        int cc = isU ? c : (c - D);
#pragma unroll
        for (int i = 0; i < 8; i++) {
            int gr = rowbase + ry * 8 + i;
            float c0, c1, c2, c3;
            unpack2(acc[i][0], c0, c1);
            unpack2(acc[i][1], c2, c3);
            c0 += bb.x; c1 += bb.y; c2 += bb.z; c3 += bb.w;
            if (isU) store_half4(U + (size_t)gr * D + cc, c0, c1, c2, c3);
            else *(float4*)&R[(size_t)gr * D + cc] = make_float4(c0, c1, c2, c3);
        }
    }
}

// ---------------- GCN prop with self loops: warp/node, fp16 gather, unroll 4 ----------------
__global__ void prop_self_kernel(const __half* __restrict__ T, const float* __restrict__ bias,
                                 float* __restrict__ out) {
    int node = blockIdx.x * 8 + (threadIdx.x >> 5);
    if (node >= NN) return;
    int lane = threadIdx.x & 31;
    int start = g_off[node] + g_part[node >> 8];
    int cnt = g_deg[node];
    float di = g_dinv_s[node];
    bool act = lane < 25;
    int col = lane * 4;
    float4 a = make_float4(0.f, 0.f, 0.f, 0.f);

    int e = 0;
    for (; e + 4 <= cnt; e += 4) {
        int j0 = g_csr[start + e];
        int j1 = g_csr[start + e + 1];
        int j2 = g_csr[start + e + 2];
        int j3 = g_csr[start + e + 3];
        float w0 = g_dinv_s[j0], w1 = g_dinv_s[j1];
        float w2 = g_dinv_s[j2], w3 = g_dinv_s[j3];
        if (act) {
            const float4 v0 = load_half4(T + (size_t)j0 * D + col);
            const float4 v1 = load_half4(T + (size_t)j1 * D + col);
            const float4 v2 = load_half4(T + (size_t)j2 * D + col);
            const float4 v3 = load_half4(T + (size_t)j3 * D + col);
            a.x = fmaf(w0, v0.x, a.x); a.y = fmaf(w0, v0.y, a.y);
            a.z = fmaf(w0, v0.z, a.z); a.w = fmaf(w0, v0.w, a.w);
            a.x = fmaf(w1, v1.x, a.x); a.y = fmaf(w1, v1.y, a.y);
            a.z = fmaf(w1, v1.z, a.z); a.w = fmaf(w1, v1.w, a.w);
            a.x = fmaf(w2, v2.x, a.x); a.y = fmaf(w2, v2.y, a.y);
            a.z = fmaf(w2, v2.z, a.z); a.w = fmaf(w2, v2.w, a.w);
            a.x = fmaf(w3, v3.x, a.x); a.y = fmaf(w3, v3.y, a.y);
            a.z = fmaf(w3, v3.z, a.z); a.w = fmaf(w3, v3.w, a.w);
        }
    }
    for (; e < cnt; e++) {
        int j = g_csr[start + e];
        float w = g_dinv_s[j];
        if (act) {
            const float4 v = load_half4(T + (size_t)j * D + col);
            a.x = fmaf(w, v.x, a.x); a.y = fmaf(w, v.y, a.y);
            a.z = fmaf(w, v.z, a.z); a.w = fmaf(w, v.w, a.w);
        }
    }
    if (act) {
        const float4 v = load_half4(T + (size_t)node * D + col);
        a.x = fmaf(di, v.x, a.x); a.y = fmaf(di, v.y, a.y);
        a.z = fmaf(di, v.z, a.z); a.w = fmaf(di, v.w, a.w);
        const float4 bb = *(const float4*)(bias + col);
        float4 o;
        o.x = fmaxf(fmaf(di, a.x, bb.x), 0.f);
        o.y = fmaxf(fmaf(di, a.y, bb.y), 0.f);
        o.z = fmaxf(fmaf(di, a.z, bb.z), 0.f);
        o.w = fmaxf(fmaf(di, a.w, bb.w), 0.f);
        *(float4*)(out + (size_t)node * D + col) = o;
    }
}

// ---------------- BatchNorm stats ----------------
__global__ void bn_stats_kernel() {
    int c = threadIdx.x;
    if (c >= D) return;
    int r0 = blockIdx.x * 256;
    int r1 = min(r0 + 256, NN);
    float s = 0.f, q = 0.f;
    for (int r = r0; r < r1; r++) {
        float v = g_h2[(size_t)r * D + c];
        s += v;
        q = fmaf(v, v, q);
    }
    atomicAdd(&g_sum[c], s);
    atomicAdd(&g_sumsq[c], q);
}

// ---------------- fold BatchNorm affine into ARMA weights (concat [Wu|Wr]) ----------------
__global__ void fold_kernel(const float* __restrict__ gamma, const float* __restrict__ beta,
                            const float* __restrict__ Wa_init, const float* __restrict__ Wa_root,
                            const float* __restrict__ ba) {
    __shared__ float s[D], t[D];
    int tid = threadIdx.x;
    if (tid < D) {
        float mu = g_sum[tid] * (1.f / NN);
        float var = g_sumsq[tid] * (1.f / NN) - mu * mu;
        float rs = rsqrtf(var + 1e-5f);
        float sv = gamma[tid] * rs;
        s[tid] = sv;
        t[tid] = beta[tid] - mu * sv;
    }
    __syncthreads();
    for (int idx = tid; idx < D * 200; idx += blockDim.x) {
        int k = idx / 200, c = idx % 200;
        float w = (c < D) ? Wa_init[k * D + c] : Wa_root[k * D + (c - D)];
        g_Wur[idx] = s[k] * w;
    }
    for (int c = tid; c < 200; c += blockDim.x) {
        float acc;
        if (c < D) {
            acc = 0.f;
            for (int k = 0; k < D; k++) acc = fmaf(t[k], Wa_init[k * D + c], acc);
        } else {
            int cc = c - D;
            acc = ba[cc];
            for (int k = 0; k < D; k++) acc = fmaf(t[k], Wa_root[k * D + cc], acc);
        }
        g_bur[c] = acc;
    }
}

// ---------------- ARMA prop (no self loops) + root + relu + block-pooled scatter ----------------
__global__ void arma_pool_kernel(const int* __restrict__ batch) {
    __shared__ float sacc[D];
    __shared__ int s_b0, s_same;
    int wid = threadIdx.x >> 5;
    int lane = threadIdx.x & 31;
    int node = blockIdx.x * 8 + wid;

    if (threadIdx.x == 0) {
        int b0 = batch[blockIdx.x * 8];
        int b7 = batch[blockIdx.x * 8 + 7];
        s_b0 = b0;
        s_same = (b0 == b7) ? 1 : 0;
    }
    if (threadIdx.x < D) sacc[threadIdx.x] = 0.f;

    int start = g_off[node] + g_part[node >> 8];
    int cnt = g_deg[node];
    float di = g_dinv_n[node];
    bool act = lane < 25;
    int col = lane * 4;
    float4 a = make_float4(0.f, 0.f, 0.f, 0.f);

    int e = 0;
    for (; e + 4 <= cnt; e += 4) {
        int j0 = g_csr[start + e];
        int j1 = g_csr[start + e + 1];
        int j2 = g_csr[start + e + 2];
        int j3 = g_csr[start + e + 3];
        float w0 = g_dinv_n[j0], w1 = g_dinv_n[j1];
        float w2 = g_dinv_n[j2], w3 = g_dinv_n[j3];
        if (act) {
            const float4 v0 = load_half4(g_u + (size_t)j0 * D + col);
            const float4 v1 = load_half4(g_u + (size_t)j1 * D + col);
            const float4 v2 = load_half4(g_u + (size_t)j2 * D + col);
            const float4 v3 = load_half4(g_u + (size_t)j3 * D + col);
            a.x = fmaf(w0, v0.x, a.x); a.y = fmaf(w0, v0.y, a.y);
            a.z = fmaf(w0, v0.z, a.z); a.w = fmaf(w0, v0.w, a.w);
            a.x = fmaf(w1, v1.x, a.x); a.y = fmaf(w1, v1.y, a.y);
            a.z = fmaf(w1, v1.z, a.z); a.w = fmaf(w1, v1.w, a.w);
            a.x = fmaf(w2, v2.x, a.x); a.y = fmaf(w2, v2.y, a.y);
            a.z = fmaf(w2, v2.z, a.z); a.w = fmaf(w2, v2.w, a.w);
            a.x = fmaf(w3, v3.x, a.x); a.y = fmaf(w3, v3.y, a.y);
            a.z = fmaf(w3, v3.z, a.z); a.w = fmaf(w3, v3.w, a.w);
        }
    }
    for (; e < cnt; e++) {
        int j = g_csr[start + e];
        float w = g_dinv_n[j];
        if (act) {
            const float4 v = load_half4(g_u + (size_t)j * D + col);
            a.x = fmaf(w, v.x, a.x); a.y = fmaf(w, v.y, a.y);
            a.z = fmaf(w, v.z, a.z); a.w = fmaf(w, v.w, a.w);
        }
    }

    float v0 = 0.f, v1 = 0.f, v2 = 0.f, v3 = 0.f;
    if (act) {
        const float4 r = *(const float4*)(g_r + (size_t)node * D + col);
        v0 = fmaxf(fmaf(di, a.x, r.x), 0.f);
        v1 = fmaxf(fmaf(di, a.y, r.y), 0.f);
        v2 = fmaxf(fmaf(di, a.z, r.z), 0.f);
        v3 = fmaxf(fmaf(di, a.w, r.w), 0.f);
    }
    __syncthreads();
    if (s_same) {
        if (act) {
            atomicAdd(&sacc[col],     v0);
            atomicAdd(&sacc[col + 1], v1);
            atomicAdd(&sacc[col + 2], v2);
            atomicAdd(&sacc[col + 3], v3);
        }
        __syncthreads();
        if (threadIdx.x < D)
            atomicAdd(&g_pool[(size_t)s_b0 * D + threadIdx.x], sacc[threadIdx.x]);
    } else {
        if (act) {
            float* p = g_pool + (size_t)batch[node] * D + col;
            atomicAdd(&p[0], v0);
            atomicAdd(&p[1], v1);
            atomicAdd(&p[2], v2);
            atomicAdd(&p[3], v3);
        }
    }
}

// ---------------- small MLP GEMM (row per block) ----------------
template <int K, int NC, bool RELU>
__global__ void mlp_gemm(const float* __restrict__ A, const float* __restrict__ W,
                         const float* __restrict__ b, float* __restrict__ C) {
    __shared__ float As[K];
    int r = blockIdx.x;
    for (int k = threadIdx.x; k < K; k += blockDim.x) As[k] = A[r * K + k];
    __syncthreads();
    for (int c = threadIdx.x; c < NC; c += blockDim.x) {
        float acc = b[c];
#pragma unroll 4
        for (int k = 0; k < K; k++) acc = fmaf(As[k], W[k * NC + c], acc);
        C[r * NC + c] = RELU ? fmaxf(acc, 0.f) : acc;
    }
}

// ---------------- host helpers ----------------
static void* symaddr_v(const void* sym) {
    void* p = nullptr;
    cudaGetSymbolAddress(&p, sym);
    return p;
}

// ---------------- launcher ----------------
extern "C" void kernel_launch(void* const* d_in, const int* in_sizes, int n_in,
                              void* d_out, int out_size) {
    const float* x       = (const float*)d_in[0];
    const int*   src     = (const int*)d_in[1];
    const int*   dst     = (const int*)d_in[2];
    const int*   batch   = (const int*)d_in[3];
    const float* W1      = (const float*)d_in[4];
    const float* b1      = (const float*)d_in[5];
    const float* W2      = (const float*)d_in[6];
    const float* b2      = (const float*)d_in[7];
    const float* gamma   = (const float*)d_in[8];
    const float* beta    = (const float*)d_in[9];
    const float* Wa_init = (const float*)d_in[10];
    const float* Wa_root = (const float*)d_in[11];
    const float* ba      = (const float*)d_in[12];
    const float* Wf1     = (const float*)d_in[13];
    const float* bf1     = (const float*)d_in[14];
    const float* Wf2     = (const float*)d_in[15];
    const float* bf2     = (const float*)d_in[16];
    const float* Wf3     = (const float*)d_in[17];
    const float* bf3     = (const float*)d_in[18];
    const float* Wf4     = (const float*)d_in[19];
    const float* bf4     = (const float*)d_in[20];
    float* out = (float*)d_out;

    __half* p_t0  = (__half*)symaddr_v(g_t0);
    float*  p_h1  = (float*)symaddr_v(g_h1);
    __half* p_t1  = (__half*)symaddr_v(g_t1);
    float*  p_h2  = (float*)symaddr_v(g_h2);
    __half* p_u   = (__half*)symaddr_v(g_u);
    float*  p_r   = (float*)symaddr_v(g_r);
    float*  p_Wur = (float*)symaddr_v(g_Wur);
    float*  p_bur = (float*)symaddr_v(g_bur);
    float*  p_pool= (float*)symaddr_v(g_pool);
    float*  p_m1  = (float*)symaddr_v(g_m1);
    float*  p_m2  = (float*)symaddr_v(g_m2);
    float*  p_m3  = (float*)symaddr_v(g_m3);

    // persistent side stream + fork/join events (created once; reused every call)
    static cudaStream_t s2 = nullptr;
    static cudaEvent_t ev_fork = nullptr, ev_join = nullptr;
    if (!s2) {
        cudaStreamCreateWithFlags(&s2, cudaStreamNonBlocking);
        cudaEventCreateWithFlags(&ev_fork, cudaEventDisableTiming);
        cudaEventCreateWithFlags(&ev_join, cudaEventDisableTiming);
    }

    const int GB_N = (NN + 255) / 256;       // 391
    const int GB_E = (EE + 255) / 256;       // 6250
    const int GB_P = (NN + 7) / 8;           // 12500 (warp per node, 8/block)
    const int GB_G = NN / 80;                // 1250 (gemm_rf2 blocks, exact)
    const int GB_U = NN / 40;                // 2500 (gemm_ur2 blocks, exact)

    // #1: init (legacy stream)
    zero_kernel<<<GB_N, 256>>>();
    // fork: graph build on side stream, overlapped with gemm1
    cudaEventRecord(ev_fork, 0);
    cudaStreamWaitEvent(s2, ev_fork, 0);
    deg_kernel<<<GB_E, 256, 0, s2>>>(dst);          // #2
    scan1_kernel<<<SCAN_B, 256, 0, s2>>>();         // #3
    // #4: SGConv-1 GEMM on legacy stream (concurrent with graph build) <- profiled
    gemm_rf2<K1, 32, true><<<GB_G, 256>>>(x, W1, nullptr, p_t0);
    scan2_kernel<<<1, 512, 0, s2>>>();              // #5
    csrfill_kernel<<<GB_E, 256, 0, s2>>>(src, dst); // #6
    cudaEventRecord(ev_join, s2);
    cudaStreamWaitEvent(0, ev_join, 0);

    // SGConv 1 propagation (needs gemm1 + graph build)
    prop_self_kernel<<<GB_P, 256>>>(p_t0, b1, p_h1);

    // SGConv 2
    gemm_rf2<D, 25, true><<<GB_G, 256>>>(p_h1, W2, nullptr, p_t1);
    prop_self_kernel<<<GB_P, 256>>>(p_t1, b2, p_h2);

    // BatchNorm stats + fold into ARMA weights
    bn_stats_kernel<<<GB_N, 128>>>();
    fold_kernel<<<1, 256>>>(gamma, beta, Wa_init, Wa_root, ba);

    // ARMA: [u | r] = h2 @ Wur + bur  (u fp16, r fp32)
    gemm_ur2<D, 25><<<GB_U, 256>>>(p_h2, p_Wur, p_bur, p_u, p_r);

    // a = relu(prop_noself(u) + r), pooled by graph id (fused, block-pooled)
    arma_pool_kernel<<<GB_P, 256>>>(batch);

    // MLP head on [512, 100]
    mlp_gemm<100, 200, true><<<NG, 256>>>(p_pool, Wf1, bf1, p_m1);
    mlp_gemm<200, 300, true><<<NG, 256>>>(p_m1, Wf2, bf2, p_m2);
    mlp_gemm<300, 200, true><<<NG, 256>>>(p_m2, Wf3, bf3, p_m3);
    mlp_gemm<200, 1, false><<<NG, 32>>>(p_m3, Wf4, bf4, out);
}